// round 15
// baseline (speedup 1.0000x reference)
#include <cuda_runtime.h>
#include <cuda_fp16.h>
#include <math.h>
#include <stdint.h>

// ---------------- problem constants ----------------
#define BSZ 32
#define TT 197           // tokens
#define TD 768           // token dim
#define NH 12            // heads
#define HD 64            // head dim
#define NB 12            // blocks
#define MD 3072          // mlp dim
#define OD 1000          // out dim
#define NPATCH 196
#define M_TOK (BSZ*TT)   // 6304
#define M_PATCH (BSZ*NPATCH) // 6272
#define ATT_SCALE 0.125f
#define LN_EPS 1e-5f

// ---------------- scratch (device globals, no allocation) ----------------
__device__ float  g_x[M_TOK*TD];
__device__ __half g_h[M_TOK*TD];
__device__ __half g_q[M_TOK*TD];       // pre-scaled by ATT_SCALE
__device__ __half g_k[M_TOK*TD];
__device__ __half g_v[M_TOK*TD];
__device__ __half g_mlp[(size_t)M_TOK*MD];
__device__ __half g_patches[(size_t)M_PATCH*TD];
__device__ float  g_tok[(size_t)M_PATCH*TD];
__device__ float  g_p0[M_TOK*TD];      // split-K partial 0
__device__ float  g_p1[M_TOK*TD];      // split-K partial 1
// packed fp16 weights, k-pair layout: element (k2, n) = (B[2k2][n], B[2k2+1][n])
#define WH_EMBED_OFF 0
#define WH_M1_OFF    (768/2*768)
#define WH_M2_OFF    (768/2*768 + 12*(768/2)*3072)
__device__ __half2 g_wH[768/2*768 + 12*(768/2)*3072 + 12*(3072/2)*768];
// packed QKV weights: [matrix(3)][layer*NH + head][k2(32)][e(64)] half2
#define QKV_HEAD_H2 (32*64)
__device__ __half2 g_wQKV[3][(size_t)NB*NH*QKV_HEAD_H2];

// ---------------- small reductions ----------------
__device__ __forceinline__ float warpSum(float v){
    #pragma unroll
    for (int o=16;o;o>>=1) v += __shfl_xor_sync(0xffffffffu, v, o);
    return v;
}
__device__ __forceinline__ float warpMax(float v){
    #pragma unroll
    for (int o=16;o;o>>=1) v = fmaxf(v, __shfl_xor_sync(0xffffffffu, v, o));
    return v;
}
__device__ __forceinline__ float blockSum256(float v){
    __shared__ float red[8];
    __shared__ float total;
    int lane = threadIdx.x & 31, w = threadIdx.x >> 5;
    v = warpSum(v);
    if (lane == 0) red[w] = v;
    __syncthreads();
    if (threadIdx.x == 0){ float s=0.f; for(int i=0;i<8;i++) s += red[i]; total = s; }
    __syncthreads();
    float r = total;
    __syncthreads();
    return r;
}
__device__ __forceinline__ float blockMax256(float v){
    __shared__ float red[8];
    __shared__ float total;
    int lane = threadIdx.x & 31, w = threadIdx.x >> 5;
    v = warpMax(v);
    if (lane == 0) red[w] = v;
    __syncthreads();
    if (threadIdx.x == 0){ float s=-1e30f; for(int i=0;i<8;i++) s = fmaxf(s, red[i]); total = s; }
    __syncthreads();
    float r = total;
    __syncthreads();
    return r;
}

// ---------------- async helpers ----------------
__device__ __forceinline__ unsigned smem_u32(const void* p){
    return (unsigned)__cvta_generic_to_shared(p);
}
__device__ __forceinline__ void cp_async16(unsigned dst, const void* src, int src_bytes){
    asm volatile("cp.async.cg.shared.global [%0], [%1], 16, %2;\n"
                 :: "r"(dst), "l"(src), "r"(src_bytes));
}
__device__ __forceinline__ void cp_commit(){ asm volatile("cp.async.commit_group;\n"); }
template<int N>
__device__ __forceinline__ void cp_wait(){ asm volatile("cp.async.wait_group %0;\n" :: "n"(N)); }

__device__ __forceinline__ void mma16816(float* c, const uint32_t* a, uint32_t b0, uint32_t b1){
    asm volatile(
        "mma.sync.aligned.m16n8k16.row.col.f32.f16.f16.f32 "
        "{%0,%1,%2,%3}, {%4,%5,%6,%7}, {%8,%9}, {%0,%1,%2,%3};"
        : "+f"(c[0]), "+f"(c[1]), "+f"(c[2]), "+f"(c[3])
        : "r"(a[0]), "r"(a[1]), "r"(a[2]), "r"(a[3]), "r"(b0), "r"(b1));
}

// ---------------- weight pack: fp32 [K][N] -> half2 k-pair [K/2][N] ----------------
__global__ void packB_kernel(const float* __restrict__ src, __half2* __restrict__ dst,
                             size_t K2, int N){
    size_t total = K2*N;
    size_t i = (size_t)blockIdx.x*blockDim.x + threadIdx.x;
    size_t stride = (size_t)gridDim.x*blockDim.x;
    for (; i < total; i += stride){
        size_t k2 = i / N;
        size_t n  = i % N;
        dst[i] = __floats2half2_rn(src[(2*k2)*N + n], src[(2*k2+1)*N + n]);
    }
}

// pack QKV: src [NB*NH][64][64] fp32 -> dst [NB*NH][32][64] half2 (k-pairs)
__global__ void pack_qkv_kernel(const float* __restrict__ src, __half2* __restrict__ dst){
    size_t total = (size_t)NB*NH*QKV_HEAD_H2;
    size_t i = (size_t)blockIdx.x*blockDim.x + threadIdx.x;
    size_t stride = (size_t)gridDim.x*blockDim.x;
    for (; i < total; i += stride){
        size_t head = i / QKV_HEAD_H2;
        int k2 = (int)((i >> 6) & 31);
        int e  = (int)(i & 63);
        const float* s = src + head*4096;
        dst[i] = __floats2half2_rn(s[(2*k2)*64 + e], s[(2*k2+1)*64 + e]);
    }
}

// ---------------- patchify (fp16 out) ----------------
__global__ void patchify_kernel(const float* __restrict__ img){
    int idx = blockIdx.x*blockDim.x + threadIdx.x;
    if (idx >= M_PATCH*TD) return;
    int d = idx % TD;
    int mp = idx / TD;
    int b = mp / NPATCH;
    int p = mp % NPATCH;
    int py = p / 14, px = p % 14;
    int c = d >> 8;
    int r = d & 255;
    int iy = r >> 4, ix = r & 15;
    g_patches[idx] = __float2half_rn(img[ (((size_t)(b*3 + c)*224) + py*16 + iy)*224 + px*16 + ix ]);
}

// ---------------- cls + pos-emb assembly ----------------
__global__ void assemble_kernel(const float* __restrict__ vcls, const float* __restrict__ tokens){
    int idx = blockIdx.x*blockDim.x + threadIdx.x;
    if (idx >= M_TOK*TD) return;
    int d = idx % TD;
    int m = idx / TD;
    int b = m / TT;
    int s = m % TT;
    float val = (s == 0) ? vcls[d] : tokens[(size_t)(b*NPATCH + s - 1)*TD + d];
    float je = (float)(d & ~1);
    float ang = (float)s * exp2f(-je * (13.287712379549449f / 197.0f));
    val += (d & 1) ? cosf(ang) : sinf(ang);
    g_x[idx] = val;
}

// ---------------- fused split-K reduce + (optional) next-layer LN1 ----------------
// x += p0 + p1 + bias; if doLN: h = LN(x)*g + b (fp16)
__global__ void __launch_bounds__(256)
mlpres_ln_kernel(const float* __restrict__ bias,
                 const float* __restrict__ g, const float* __restrict__ b, int doLN){
    __shared__ float4 sdata[192];
    int row = blockIdx.x;
    int tid = threadIdx.x;
    size_t i = (size_t)row*192 + tid;
    float4 xn = make_float4(0.f,0.f,0.f,0.f);
    float local = 0.f;
    if (tid < 192){
        float4 xv = ((const float4*)g_x)[i];
        float4 a  = ((const float4*)g_p0)[i];
        float4 bv = ((const float4*)g_p1)[i];
        float4 bb = ((const float4*)bias)[tid];
        xn.x = xv.x + a.x + bv.x + bb.x;
        xn.y = xv.y + a.y + bv.y + bb.y;
        xn.z = xv.z + a.z + bv.z + bb.z;
        xn.w = xv.w + a.w + bv.w + bb.w;
        ((float4*)g_x)[i] = xn;
        sdata[tid] = xn;
        local = xn.x + xn.y + xn.z + xn.w;
    }
    if (!doLN) return;   // uniform across block: no thread reaches barriers below
    float mean = blockSum256(local) * (1.0f/TD);
    float lv = 0.f;
    if (tid < 192){
        float4 t = sdata[tid];
        float a0 = t.x-mean, a1 = t.y-mean, a2 = t.z-mean, a3 = t.w-mean;
        lv = a0*a0 + a1*a1 + a2*a2 + a3*a3;
    }
    float var = blockSum256(lv) * (1.0f/TD);
    float rstd = rsqrtf(var + LN_EPS);
    if (tid < 192){
        float4 gg = ((const float4*)g)[tid];
        float4 bb = ((const float4*)b)[tid];
        float o0 = (xn.x-mean)*rstd*gg.x + bb.x;
        float o1 = (xn.y-mean)*rstd*gg.y + bb.y;
        float o2 = (xn.z-mean)*rstd*gg.z + bb.z;
        float o3 = (xn.w-mean)*rstd*gg.w + bb.w;
        __half2* orow = (__half2*)(g_h + (size_t)row*TD);
        orow[tid*2    ] = __floats2half2_rn(o0, o1);
        orow[tid*2 + 1] = __floats2half2_rn(o2, o3);
    }
}

// ---------------- layernorm (vectorized, fp16 out) ----------------
__global__ void __launch_bounds__(256)
layernorm_kernel(const float* __restrict__ x, __half* __restrict__ out,
                 const float* __restrict__ g, const float* __restrict__ b){
    __shared__ float4 sdata[192];
    int row = blockIdx.x;
    int tid = threadIdx.x;
    const float4* xr = (const float4*)(x + (size_t)row*TD);
    float4 v = make_float4(0.f,0.f,0.f,0.f);
    float local = 0.f;
    if (tid < 192){ v = xr[tid]; sdata[tid] = v; local = v.x + v.y + v.z + v.w; }
    float mean = blockSum256(local) * (1.0f/TD);
    float lv = 0.f;
    if (tid < 192){
        float4 t = sdata[tid];
        float a0 = t.x-mean, a1 = t.y-mean, a2 = t.z-mean, a3 = t.w-mean;
        lv = a0*a0 + a1*a1 + a2*a2 + a3*a3;
    }
    float var = blockSum256(lv) * (1.0f/TD);
    float rstd = rsqrtf(var + LN_EPS);
    if (tid < 192){
        float4 gg = ((const float4*)g)[tid];
        float4 bb = ((const float4*)b)[tid];
        float o0 = (v.x-mean)*rstd*gg.x + bb.x;
        float o1 = (v.y-mean)*rstd*gg.y + bb.y;
        float o2 = (v.z-mean)*rstd*gg.z + bb.z;
        float o3 = (v.w-mean)*rstd*gg.w + bb.w;
        __half2* orow = (__half2*)(out + (size_t)row*TD);
        orow[tid*2    ] = __floats2half2_rn(o0, o1);
        orow[tid*2 + 1] = __floats2half2_rn(o2, o3);
    }
}

// ---------------- QKV projection via fp16 MMA (fp16 out, q pre-scaled) ----------------
__global__ void __launch_bounds__(256)
qkv16_kernel(const float* __restrict__ bq, const float* __restrict__ bk,
             const float* __restrict__ bv, int layer){
    __shared__ __half  Hs[128][72];
    __shared__ __half2 Ws[3][32][72];

    int h = blockIdx.y;
    int m0 = blockIdx.x * 128;
    int tid = threadIdx.x;
    int warp = tid >> 5, lane = tid & 31;

    int hrow = tid >> 1;
    int hcol = (tid & 1) * 32;
    const __half* hSrc = g_h + (size_t)(m0 + hrow)*TD + h*64 + hcol;
    int hSz = (m0 + hrow < M_TOK) ? 16 : 0;
    #pragma unroll
    for (int c = 0; c < 4; c++)
        cp_async16(smem_u32(&Hs[hrow][hcol + c*8]), hSrc + c*8, hSz);

    size_t head_off = ((size_t)layer*NH + h)*QKV_HEAD_H2;
    #pragma unroll
    for (int mt = 0; mt < 3; mt++){
        const __half2* wsrc = g_wQKV[mt] + head_off;
        #pragma unroll
        for (int c = 0; c < 2; c++){
            int ch = tid + c*256;
            int r  = ch >> 4;
            int c4 = (ch & 15) * 4;
            cp_async16(smem_u32(&Ws[mt][r][c4]), wsrc + r*64 + c4, 16);
        }
    }
    cp_commit();
    cp_wait<0>();
    __syncthreads();

    float cf[3][8][4];
    #pragma unroll
    for (int mt=0;mt<3;mt++)
        #pragma unroll
        for (int ni=0;ni<8;ni++)
            #pragma unroll
            for (int j=0;j<4;j++) cf[mt][ni][j] = 0.f;

    int q2 = (lane & 3) * 2;
    #pragma unroll
    for (int ks = 0; ks < 64; ks += 16){
        uint32_t af[4];
        int m = warp*16 + (lane >> 2);
        af[0] = *(const uint32_t*)&Hs[m  ][ks + q2];
        af[1] = *(const uint32_t*)&Hs[m+8][ks + q2];
        af[2] = *(const uint32_t*)&Hs[m  ][ks + 8 + q2];
        af[3] = *(const uint32_t*)&Hs[m+8][ks + 8 + q2];
        int k2r = (ks >> 1) + (lane & 3);
        #pragma unroll
        for (int mt = 0; mt < 3; mt++){
            #pragma unroll
            for (int ni = 0; ni < 8; ni++){
                int n = ni*8 + (lane >> 2);
                uint32_t b0 = *(const uint32_t*)&Ws[mt][k2r    ][n];
                uint32_t b1 = *(const uint32_t*)&Ws[mt][k2r + 4][n];
                mma16816(cf[mt][ni], af, b0, b1);
            }
        }
    }

    const float* bp[3] = {bq + h*64, bk + h*64, bv + h*64};
    __half* op[3] = {g_q, g_k, g_v};
    float scale[3] = {ATT_SCALE, 1.0f, 1.0f};
    #pragma unroll
    for (int mt = 0; mt < 3; mt++){
        #pragma unroll
        for (int ni = 0; ni < 8; ni++){
            int cbase = ni*8 + (lane & 3)*2;
            #pragma unroll
            for (int hh = 0; hh < 2; hh++){
                int r = m0 + warp*16 + (lane >> 2) + hh*8;
                if (r >= M_TOK) continue;
                int e = cbase;
                __half2 hv = __floats2half2_rn(
                    (cf[mt][ni][hh*2+0] + bp[mt][e    ]) * scale[mt],
                    (cf[mt][ni][hh*2+1] + bp[mt][e + 1]) * scale[mt]);
                *(__half2*)&op[mt][(size_t)r*TD + h*64 + e] = hv;
            }
        }
    }
}

// ---------------- flash attention via fp16 MMA ----------------
#define FATT_SMEM ((128*72 + 208*72 + 64*216)*2)

__global__ void __launch_bounds__(256)
fattn_kernel(){
    extern __shared__ __half fsm[];
    __half* Qs = fsm;                    // [128][72]
    __half* Ks = Qs + 128*72;            // [208][72]
    __half* Vt = Ks + 208*72;            // [64][216]

    int h = blockIdx.x, b = blockIdx.y, qz = blockIdx.z;
    int tid = threadIdx.x, warp = tid >> 5, lane = tid & 31;
    size_t base = ((size_t)b*TT)*TD + h*64;
    int q0cta = qz*128;

    for (int i = tid; i < 128*8; i += 256){
        int r = i >> 3, c = i & 7;
        int qrow = q0cta + r;
        const __half* src = g_q + base + (size_t)((qrow < TT) ? qrow : 0)*TD + c*8;
        cp_async16(smem_u32(&Qs[r*72 + c*8]), src, (qrow < TT) ? 16 : 0);
    }
    for (int i = tid; i < 208*8; i += 256){
        int r = i >> 3, c = i & 7;
        const __half* src = g_k + base + (size_t)((r < TT) ? r : 0)*TD + c*8;
        cp_async16(smem_u32(&Ks[r*72 + c*8]), src, (r < TT) ? 16 : 0);
    }
    cp_commit();
    for (int i = tid; i < 208*32; i += 256){
        int r = i >> 5, dp = (i & 31)*2;
        __half2 hv;
        if (r < TT) hv = *(const __half2*)(g_v + base + (size_t)r*TD + dp);
        else        hv = __floats2half2_rn(0.f, 0.f);
        Vt[ dp     *216 + r] = __low2half(hv);
        Vt[(dp + 1)*216 + r] = __high2half(hv);
    }
    cp_wait<0>();
    __syncthreads();

    int q0 = q0cta + warp*16;
    if (q0 >= TT) return;

    int r = lane >> 2, c2 = (lane & 3)*2;

    uint32_t aq[4][4];
    #pragma unroll
    for (int ks = 0; ks < 4; ks++){
        int qr = warp*16 + r;
        aq[ks][0] = *(const uint32_t*)&Qs[ qr     *72 + ks*16 + c2];
        aq[ks][1] = *(const uint32_t*)&Qs[(qr + 8)*72 + ks*16 + c2];
        aq[ks][2] = *(const uint32_t*)&Qs[ qr     *72 + ks*16 + c2 + 8];
        aq[ks][3] = *(const uint32_t*)&Qs[(qr + 8)*72 + ks*16 + c2 + 8];
    }

    float m0 = -1e30f, m1 = -1e30f, l0 = 0.f, l1 = 0.f;
    float o[8][4];
    #pragma unroll
    for (int nt=0;nt<8;nt++)
        #pragma unroll
        for (int j=0;j<4;j++) o[nt][j] = 0.f;

    for (int kt = 0; kt < 13; kt++){
        float s0[4] = {0.f,0.f,0.f,0.f};
        float s1[4] = {0.f,0.f,0.f,0.f};
        #pragma unroll
        for (int ks = 0; ks < 4; ks++){
            int kr = kt*16 + r;
            uint32_t b00 = *(const uint32_t*)&Ks[ kr     *72 + ks*16 + c2];
            uint32_t b01 = *(const uint32_t*)&Ks[ kr     *72 + ks*16 + c2 + 8];
            uint32_t b10 = *(const uint32_t*)&Ks[(kr + 8)*72 + ks*16 + c2];
            uint32_t b11 = *(const uint32_t*)&Ks[(kr + 8)*72 + ks*16 + c2 + 8];
            mma16816(s0, aq[ks], b00, b01);
            mma16816(s1, aq[ks], b10, b11);
        }
        if (kt == 12){
            #pragma unroll
            for (int j = 0; j < 2; j++){
                if (192 + c2 + j >= TT){ s0[j] = -1e30f; s0[j+2] = -1e30f; }
                if (200 + c2 + j >= TT){ s1[j] = -1e30f; s1[j+2] = -1e30f; }
            }
        }
        float tm0 = fmaxf(fmaxf(s0[0], s0[1]), fmaxf(s1[0], s1[1]));
        float tm1 = fmaxf(fmaxf(s0[2], s0[3]), fmaxf(s1[2], s1[3]));
        tm0 = fmaxf(tm0, __shfl_xor_sync(0xffffffffu, tm0, 1));
        tm0 = fmaxf(tm0, __shfl_xor_sync(0xffffffffu, tm0, 2));
        tm1 = fmaxf(tm1, __shfl_xor_sync(0xffffffffu, tm1, 1));
        tm1 = fmaxf(tm1, __shfl_xor_sync(0xffffffffu, tm1, 2));
        float nm0 = fmaxf(m0, tm0), nm1 = fmaxf(m1, tm1);
        float cr0 = __expf(m0 - nm0), cr1 = __expf(m1 - nm1);
        m0 = nm0; m1 = nm1;
        float p00 = __expf(s0[0] - m0), p01 = __expf(s0[1] - m0);
        float p02 = __expf(s0[2] - m1), p03 = __expf(s0[3] - m1);
        float p10 = __expf(s1[0] - m0), p11 = __expf(s1[1] - m0);
        float p12 = __expf(s1[2] - m1), p13 = __expf(s1[3] - m1);
        float sum0 = p00 + p01 + p10 + p11;
        float sum1 = p02 + p03 + p12 + p13;
        sum0 += __shfl_xor_sync(0xffffffffu, sum0, 1);
        sum0 += __shfl_xor_sync(0xffffffffu, sum0, 2);
        sum1 += __shfl_xor_sync(0xffffffffu, sum1, 1);
        sum1 += __shfl_xor_sync(0xffffffffu, sum1, 2);
        l0 = l0*cr0 + sum0;
        l1 = l1*cr1 + sum1;
        #pragma unroll
        for (int nt = 0; nt < 8; nt++){
            o[nt][0] *= cr0; o[nt][1] *= cr0;
            o[nt][2] *= cr1; o[nt][3] *= cr1;
        }
        uint32_t pa[4];
        __half2 h0 = __floats2half2_rn(p00, p01);
        __half2 h1 = __floats2half2_rn(p02, p03);
        __half2 h2 = __floats2half2_rn(p10, p11);
        __half2 h3 = __floats2half2_rn(p12, p13);
        pa[0] = *(uint32_t*)&h0; pa[1] = *(uint32_t*)&h1;
        pa[2] = *(uint32_t*)&h2; pa[3] = *(uint32_t*)&h3;
        #pragma unroll
        for (int nt = 0; nt < 8; nt++){
            int vrow = nt*8 + r;
            uint32_t b0 = *(const uint32_t*)&Vt[vrow*216 + kt*16 + c2];
            uint32_t b1 = *(const uint32_t*)&Vt[vrow*216 + kt*16 + c2 + 8];
            mma16816(o[nt], pa, b0, b1);
        }
    }

    float inv0 = 1.0f / l0, inv1 = 1.0f / l1;
    int qa = q0 + r, qb = q0 + r + 8;
    #pragma unroll
    for (int nt = 0; nt < 8; nt++){
        int d = nt*8 + c2;
        if (qa < TT){
            g_x[base + (size_t)qa*TD + d    ] += o[nt][0]*inv0;
            g_x[base + (size_t)qa*TD + d + 1] += o[nt][1]*inv0;
        }
        if (qb < TT){
            g_x[base + (size_t)qb*TD + d    ] += o[nt][2]*inv1;
            g_x[base + (size_t)qb*TD + d + 1] += o[nt][3]*inv1;
        }
    }
}

// ---------------- fp16 GEMM: k-tile 64, 3-stage ring, 2 CTA/SM, optional split-K ----------------
// A row stride = lda (halves). Processes K columns starting at blockIdx.z*K.
// epi: 0 fp32 store +bias, 1 gelu->half +bias, 2 fp32 residual += +bias,
//      3 split-K raw partial (z=0 -> C, z=1 -> Cp1, no bias).
// Stage: As[128][72] half (18432B) + Bs[32][136] half2 (17408B) = 35840B; 3 stages.
#define H16_A_BYTES (128*72*2)
#define H16_STAGE_BYTES (128*72*2 + 32*136*4)
#define H16_SMEM (3*H16_STAGE_BYTES)

__global__ void __launch_bounds__(256, 2)
h16gemm_kernel(const __half* __restrict__ A, int lda,
               const __half2* __restrict__ Bp,
               const float* __restrict__ bias, void* __restrict__ C,
               float* __restrict__ Cp1,
               int M, int N, int K, int epi){
    extern __shared__ char smg[];

    int tid  = threadIdx.x;
    int lane = tid & 31;
    int warp = tid >> 5;
    int warpM = warp >> 1;
    int warpN = warp & 1;
    int row0 = blockIdx.y * 128;
    int col0 = blockIdx.x * 128;
    int kOff = blockIdx.z * K;

    float cf[2][8][4];
    #pragma unroll
    for (int mi=0;mi<2;mi++)
        #pragma unroll
        for (int ni=0;ni<8;ni++)
            #pragma unroll
            for (int j=0;j<4;j++) cf[mi][ni][j] = 0.f;

    // A loader: thread t -> row t>>1, half-col (t&1)*32, 4 chunks of 8 halves
    int arow = tid >> 1;
    int acol = (tid & 1) * 32;
    const __half* aSrc = A + (size_t)(row0 + arow)*lda + kOff + acol;
    int aSz = (row0 + arow < M) ? 16 : 0;
    // B loader: thread t -> k2-row t>>3 (0..31), half2-col (t&7)*16, 4 chunks of 4 half2
    int bkr = tid >> 3;
    int bcc = (tid & 7) * 16;
    const __half2* bSrc = Bp + (size_t)(bkr + blockIdx.z*(K >> 1))*N + col0 + bcc;

    int KT = K >> 6;

    #pragma unroll
    for (int s = 0; s < 2; s++){
        __half*  As = (__half*)(smg + s*H16_STAGE_BYTES);
        __half2* Bs = (__half2*)(smg + s*H16_STAGE_BYTES + H16_A_BYTES);
        int kk = s << 6;
        int k2 = s << 5;
        #pragma unroll
        for (int c = 0; c < 4; c++){
            cp_async16(smem_u32(&As[arow*72 + acol + c*8]), aSrc + kk + c*8, aSz);
            cp_async16(smem_u32(&Bs[bkr*136 + bcc + c*4]), bSrc + (size_t)k2*N + c*4, 16);
        }
        cp_commit();
    }

    int stage = 0;
    for (int kt = 0; kt < KT; kt++){
        cp_wait<1>();
        __syncthreads();

        if (kt + 2 < KT){
            int st = stage + 2; if (st >= 3) st -= 3;
            __half*  Asp = (__half*)(smg + st*H16_STAGE_BYTES);
            __half2* Bsp = (__half2*)(smg + st*H16_STAGE_BYTES + H16_A_BYTES);
            int kk = (kt + 2) << 6;
            int k2 = (kt + 2) << 5;
            #pragma unroll
            for (int c = 0; c < 4; c++){
                cp_async16(smem_u32(&Asp[arow*72 + acol + c*8]), aSrc + kk + c*8, aSz);
                cp_async16(smem_u32(&Bsp[bkr*136 + bcc + c*4]), bSrc + (size_t)k2*N + c*4, 16);
            }
        }
        cp_commit();

        const __half*  As = (const __half*)(smg + stage*H16_STAGE_BYTES);
        const __half2* Bs = (const __half2*)(smg + stage*H16_STAGE_BYTES + H16_A_BYTES);

        int q2 = (lane & 3) * 2;
        #pragma unroll
        for (int ks = 0; ks < 64; ks += 16){
            uint32_t af[2][4], bf[8][2];
            #pragma unroll
            for (int mi = 0; mi < 2; mi++){
                int m = warpM*32 + mi*16 + (lane >> 2);
                af[mi][0] = *(const uint32_t*)&As[m*72 + ks + q2];
                af[mi][1] = *(const uint32_t*)&As[(m+8)*72 + ks + q2];
                af[mi][2] = *(const uint32_t*)&As[m*72 + ks + 8 + q2];
                af[mi][3] = *(const uint32_t*)&As[(m+8)*72 + ks + 8 + q2];
            }
            int k2r = (ks >> 1) + (lane & 3);
            #pragma unroll
            for (int ni = 0; ni < 8; ni++){
                int n = warpN*64 + ni*8 + (lane >> 2);
                bf[ni][0] = *(const uint32_t*)&Bs[k2r*136 + n];
                bf[ni][1] = *(const uint32_t*)&Bs[(k2r + 4)*136 + n];
            }
            #pragma unroll
            for (int mi = 0; mi < 2; mi++)
                #pragma unroll
                for (int ni = 0; ni < 8; ni++)
                    mma16816(cf[mi][ni], af[mi], bf[ni][0], bf[ni][1]);
        }
        stage++; if (stage >= 3) stage = 0;
    }

    float* Cf = (float*)C;
    __half* Ch = (__half*)C;
    float* Cpart = (blockIdx.z == 0) ? (float*)C : Cp1;
    #pragma unroll
    for (int mi = 0; mi < 2; mi++){
        int rbase = row0 + warpM*32 + mi*16 + (lane >> 2);
        #pragma unroll
        for (int ni = 0; ni < 8; ni++){
            int cbase = col0 + warpN*64 + ni*8 + (lane & 3)*2;
            #pragma unroll
            for (int hh = 0; hh < 2; hh++){
                int r = rbase + hh*8;
                if (r >= M) continue;
                #pragma unroll
                for (int jj = 0; jj < 2; jj++){
                    int c = cbase + jj;
                    size_t idx = (size_t)r*N + c;
                    if (epi == 3){
                        Cpart[idx] = cf[mi][ni][hh*2+jj];
                    } else {
                        float v = cf[mi][ni][hh*2+jj] + bias[c];
                        if (epi == 1){
                            Ch[idx] = __float2half_rn(0.5f*v*(1.0f + erff(v*0.70710678118654752f)));
                        } else if (epi == 2){
                            Cf[idx] += v;
                        } else {
                            Cf[idx] = v;
                        }
                    }
                }
            }
        }
    }
}

// ---------------- classifier head + softmax ----------------
__global__ void classifier_kernel(const float* __restrict__ Wout, const float* __restrict__ bout,
                                  float* __restrict__ out){
    __shared__ float xs[TD];
    __shared__ float lg[OD];
    int b = blockIdx.x;
    int tid = threadIdx.x;
    for (int i = tid; i < TD; i += 256) xs[i] = g_x[((size_t)b*TT)*TD + i];
    __syncthreads();
    for (int n = tid; n < OD; n += 256){
        float s = bout[n];
        for (int d = 0; d < TD; d++) s = fmaf(xs[d], Wout[(size_t)d*OD + n], s);
        lg[n] = s;
    }
    __syncthreads();
    float lm = -1e30f;
    for (int n = tid; n < OD; n += 256) lm = fmaxf(lm, lg[n]);
    lm = blockMax256(lm);
    float ls = 0.f;
    for (int n = tid; n < OD; n += 256){
        float e = expf(lg[n] - lm);
        lg[n] = e;
        ls += e;
    }
    ls = blockSum256(ls);
    float inv = 1.0f / ls;
    for (int n = tid; n < OD; n += 256) out[(size_t)b*OD + n] = lg[n] * inv;
}

// ---------------- host orchestration ----------------
extern "C" void kernel_launch(void* const* d_in, const int* in_sizes, int n_in,
                              void* d_out, int out_size){
    const float* images  = (const float*)d_in[0];
    const float* W_embed = (const float*)d_in[1];
    const float* b_embed = (const float*)d_in[2];
    const float* v_class = (const float*)d_in[3];
    const float* ln1_g   = (const float*)d_in[4];
    const float* ln1_b   = (const float*)d_in[5];
    const float* ln2_g   = (const float*)d_in[6];
    const float* ln2_b   = (const float*)d_in[7];
    const float* Wq      = (const float*)d_in[8];
    const float* bq      = (const float*)d_in[9];
    const float* Wk      = (const float*)d_in[10];
    const float* bk      = (const float*)d_in[11];
    const float* Wv      = (const float*)d_in[12];
    const float* bv      = (const float*)d_in[13];
    const float* Wm1     = (const float*)d_in[14];
    const float* bm1     = (const float*)d_in[15];
    const float* Wm2     = (const float*)d_in[16];
    const float* bm2     = (const float*)d_in[17];
    const float* Wout    = (const float*)d_in[18];
    const float* bout    = (const float*)d_in[19];
    float* out = (float*)d_out;

    float *px, *ptok, *pp0, *pp1;
    __half *ph, *pmlp, *ppatch;
    __half2 *pwH, *pwQKV0, *pwQKV1, *pwQKV2;
    cudaGetSymbolAddress((void**)&px, g_x);
    cudaGetSymbolAddress((void**)&ph, g_h);
    cudaGetSymbolAddress((void**)&pmlp, g_mlp);
    cudaGetSymbolAddress((void**)&ppatch, g_patches);
    cudaGetSymbolAddress((void**)&ptok, g_tok);
    cudaGetSymbolAddress((void**)&pp0, g_p0);
    cudaGetSymbolAddress((void**)&pp1, g_p1);
    cudaGetSymbolAddress((void**)&pwH, g_wH);
    {
        __half2* base;
        cudaGetSymbolAddress((void**)&base, g_wQKV);
        pwQKV0 = base;
        pwQKV1 = base + (size_t)NB*NH*QKV_HEAD_H2;
        pwQKV2 = base + 2*(size_t)NB*NH*QKV_HEAD_H2;
    }

    cudaFuncSetAttribute(h16gemm_kernel, cudaFuncAttributeMaxDynamicSharedMemorySize, H16_SMEM);
    cudaFuncSetAttribute(fattn_kernel, cudaFuncAttributeMaxDynamicSharedMemorySize, FATT_SMEM);

    // pack weights once per launch
    packB_kernel<<<2048, 256>>>(W_embed, pwH + WH_EMBED_OFF, (size_t)TD/2, TD);
    packB_kernel<<<16384, 256>>>(Wm1, pwH + WH_M1_OFF, (size_t)NB*TD/2, MD);
    packB_kernel<<<16384, 256>>>(Wm2, pwH + WH_M2_OFF, (size_t)NB*MD/2, TD);
    pack_qkv_kernel<<<1152, 256>>>(Wq, pwQKV0);
    pack_qkv_kernel<<<1152, 256>>>(Wk, pwQKV1);
    pack_qkv_kernel<<<1152, 256>>>(Wv, pwQKV2);

    // patchify + embed
    patchify_kernel<<<(M_PATCH*TD + 255)/256, 256>>>(images);
    {
        dim3 g(TD/128, (M_PATCH + 127)/128, 1);
        h16gemm_kernel<<<g, 256, H16_SMEM>>>(ppatch, TD, pwH + WH_EMBED_OFF, b_embed,
                                             ptok, nullptr, M_PATCH, TD, TD, 0);
    }
    assemble_kernel<<<(M_TOK*TD + 255)/256, 256>>>(v_class, ptok);

    // LN1 for layer 0
    layernorm_kernel<<<M_TOK, 256>>>(px, ph, ln1_g, ln1_b);

    for (int l = 0; l < NB; l++){
        {
            dim3 g((M_TOK + 127)/128, NH);
            qkv16_kernel<<<g, 256>>>(bq + (size_t)l*NH*64, bk + (size_t)l*NH*64,
                                     bv + (size_t)l*NH*64, l);
        }
        fattn_kernel<<<dim3(NH, BSZ, 2), 256, FATT_SMEM>>>();
        layernorm_kernel<<<M_TOK, 256>>>(px, ph, ln2_g + l*TD, ln2_b + l*TD);
        {
            dim3 g(MD/128, (M_TOK + 127)/128, 1);
            h16gemm_kernel<<<g, 256, H16_SMEM>>>(ph, TD, pwH + WH_M1_OFF + (size_t)l*(TD/2)*MD,
                                                 bm1 + (size_t)l*MD, pmlp, nullptr,
                                                 M_TOK, MD, TD, 1);
        }
        {
            dim3 g(TD/128, (M_TOK + 127)/128, 2);
            h16gemm_kernel<<<g, 256, H16_SMEM>>>(pmlp, MD, pwH + WH_M2_OFF + (size_t)l*(MD/2)*TD,
                                                 nullptr, pp0, pp1,
                                                 M_TOK, TD, MD/2, 3);
        }
        // fused: x += p0+p1+bm2; if not last layer, also h = LN1_{l+1}(x)
        if (l + 1 < NB){
            mlpres_ln_kernel<<<M_TOK, 256>>>(bm2 + (size_t)l*TD,
                                             ln1_g + (size_t)(l+1)*TD,
                                             ln1_b + (size_t)(l+1)*TD, 1);
        } else {
            mlpres_ln_kernel<<<M_TOK, 256>>>(bm2 + (size_t)l*TD, nullptr, nullptr, 0);
        }
    }

    classifier_kernel<<<BSZ, 256>>>(Wout, bout, out);
}

// round 16
// speedup vs baseline: 1.0843x; 1.0843x over previous
#include <cuda_runtime.h>
#include <cuda_fp16.h>
#include <math.h>
#include <stdint.h>

// ---------------- problem constants ----------------
#define BSZ 32
#define TT 197           // tokens
#define TD 768           // token dim
#define NH 12            // heads
#define HD 64            // head dim
#define NB 12            // blocks
#define MD 3072          // mlp dim
#define OD 1000          // out dim
#define NPATCH 196
#define M_TOK (BSZ*TT)   // 6304
#define M_PATCH (BSZ*NPATCH) // 6272
#define ATT_SCALE 0.125f
#define LN_EPS 1e-5f

// ---------------- scratch (device globals, no allocation) ----------------
__device__ float  g_x[M_TOK*TD];
__device__ __half g_h[M_TOK*TD];
__device__ __half g_q[M_TOK*TD];       // pre-scaled by ATT_SCALE
__device__ __half g_k[M_TOK*TD];
__device__ __half g_v[M_TOK*TD];
__device__ __half g_mlp[(size_t)M_TOK*MD];
__device__ __half g_patches[(size_t)M_PATCH*TD];
__device__ float  g_tok[(size_t)M_PATCH*TD];
__device__ float  g_p0[M_TOK*TD];      // split-K partial 0
__device__ float  g_p1[M_TOK*TD];      // split-K partial 1
// packed fp16 weights, k-pair layout: element (k2, n) = (B[2k2][n], B[2k2+1][n])
#define WH_EMBED_OFF 0
#define WH_M1_OFF    (768/2*768)
#define WH_M2_OFF    (768/2*768 + 12*(768/2)*3072)
__device__ __half2 g_wH[768/2*768 + 12*(768/2)*3072 + 12*(3072/2)*768];
// packed QKV weights: [matrix(3)][layer*NH + head][k2(32)][e(64)] half2
#define QKV_HEAD_H2 (32*64)
__device__ __half2 g_wQKV[3][(size_t)NB*NH*QKV_HEAD_H2];

// ---------------- small reductions ----------------
__device__ __forceinline__ float warpSum(float v){
    #pragma unroll
    for (int o=16;o;o>>=1) v += __shfl_xor_sync(0xffffffffu, v, o);
    return v;
}
__device__ __forceinline__ float warpMax(float v){
    #pragma unroll
    for (int o=16;o;o>>=1) v = fmaxf(v, __shfl_xor_sync(0xffffffffu, v, o));
    return v;
}
__device__ __forceinline__ float blockSum256(float v){
    __shared__ float red[8];
    __shared__ float total;
    int lane = threadIdx.x & 31, w = threadIdx.x >> 5;
    v = warpSum(v);
    if (lane == 0) red[w] = v;
    __syncthreads();
    if (threadIdx.x == 0){ float s=0.f; for(int i=0;i<8;i++) s += red[i]; total = s; }
    __syncthreads();
    float r = total;
    __syncthreads();
    return r;
}
__device__ __forceinline__ float blockMax256(float v){
    __shared__ float red[8];
    __shared__ float total;
    int lane = threadIdx.x & 31, w = threadIdx.x >> 5;
    v = warpMax(v);
    if (lane == 0) red[w] = v;
    __syncthreads();
    if (threadIdx.x == 0){ float s=-1e30f; for(int i=0;i<8;i++) s = fmaxf(s, red[i]); total = s; }
    __syncthreads();
    float r = total;
    __syncthreads();
    return r;
}

// ---------------- async helpers ----------------
__device__ __forceinline__ unsigned smem_u32(const void* p){
    return (unsigned)__cvta_generic_to_shared(p);
}
__device__ __forceinline__ void cp_async16(unsigned dst, const void* src, int src_bytes){
    asm volatile("cp.async.cg.shared.global [%0], [%1], 16, %2;\n"
                 :: "r"(dst), "l"(src), "r"(src_bytes));
}
__device__ __forceinline__ void cp_commit(){ asm volatile("cp.async.commit_group;\n"); }
template<int N>
__device__ __forceinline__ void cp_wait(){ asm volatile("cp.async.wait_group %0;\n" :: "n"(N)); }

__device__ __forceinline__ void mma16816(float* c, const uint32_t* a, uint32_t b0, uint32_t b1){
    asm volatile(
        "mma.sync.aligned.m16n8k16.row.col.f32.f16.f16.f32 "
        "{%0,%1,%2,%3}, {%4,%5,%6,%7}, {%8,%9}, {%0,%1,%2,%3};"
        : "+f"(c[0]), "+f"(c[1]), "+f"(c[2]), "+f"(c[3])
        : "r"(a[0]), "r"(a[1]), "r"(a[2]), "r"(a[3]), "r"(b0), "r"(b1));
}

// ---------------- weight pack: fp32 [K][N] -> half2 k-pair [K/2][N] ----------------
__global__ void packB_kernel(const float* __restrict__ src, __half2* __restrict__ dst,
                             size_t K2, int N){
    size_t total = K2*N;
    size_t i = (size_t)blockIdx.x*blockDim.x + threadIdx.x;
    size_t stride = (size_t)gridDim.x*blockDim.x;
    for (; i < total; i += stride){
        size_t k2 = i / N;
        size_t n  = i % N;
        dst[i] = __floats2half2_rn(src[(2*k2)*N + n], src[(2*k2+1)*N + n]);
    }
}

// pack QKV: src [NB*NH][64][64] fp32 -> dst [NB*NH][32][64] half2 (k-pairs)
__global__ void pack_qkv_kernel(const float* __restrict__ src, __half2* __restrict__ dst){
    size_t total = (size_t)NB*NH*QKV_HEAD_H2;
    size_t i = (size_t)blockIdx.x*blockDim.x + threadIdx.x;
    size_t stride = (size_t)gridDim.x*blockDim.x;
    for (; i < total; i += stride){
        size_t head = i / QKV_HEAD_H2;
        int k2 = (int)((i >> 6) & 31);
        int e  = (int)(i & 63);
        const float* s = src + head*4096;
        dst[i] = __floats2half2_rn(s[(2*k2)*64 + e], s[(2*k2+1)*64 + e]);
    }
}

// ---------------- patchify (fp16 out) ----------------
__global__ void patchify_kernel(const float* __restrict__ img){
    int idx = blockIdx.x*blockDim.x + threadIdx.x;
    if (idx >= M_PATCH*TD) return;
    int d = idx % TD;
    int mp = idx / TD;
    int b = mp / NPATCH;
    int p = mp % NPATCH;
    int py = p / 14, px = p % 14;
    int c = d >> 8;
    int r = d & 255;
    int iy = r >> 4, ix = r & 15;
    g_patches[idx] = __float2half_rn(img[ (((size_t)(b*3 + c)*224) + py*16 + iy)*224 + px*16 + ix ]);
}

// ---------------- cls + pos-emb assembly ----------------
__global__ void assemble_kernel(const float* __restrict__ vcls, const float* __restrict__ tokens){
    int idx = blockIdx.x*blockDim.x + threadIdx.x;
    if (idx >= M_TOK*TD) return;
    int d = idx % TD;
    int m = idx / TD;
    int b = m / TT;
    int s = m % TT;
    float val = (s == 0) ? vcls[d] : tokens[(size_t)(b*NPATCH + s - 1)*TD + d];
    float je = (float)(d & ~1);
    float ang = (float)s * exp2f(-je * (13.287712379549449f / 197.0f));
    val += (d & 1) ? cosf(ang) : sinf(ang);
    g_x[idx] = val;
}

// ---------------- fused split-K reduce + (optional) next-layer LN1 ----------------
// x += p0 + p1 + bias; if doLN: h = LN(x)*g + b (fp16)
__global__ void __launch_bounds__(256)
mlpres_ln_kernel(const float* __restrict__ bias,
                 const float* __restrict__ g, const float* __restrict__ b, int doLN){
    __shared__ float4 sdata[192];
    int row = blockIdx.x;
    int tid = threadIdx.x;
    size_t i = (size_t)row*192 + tid;
    float4 xn = make_float4(0.f,0.f,0.f,0.f);
    float local = 0.f;
    if (tid < 192){
        float4 xv = ((const float4*)g_x)[i];
        float4 a  = ((const float4*)g_p0)[i];
        float4 bv = ((const float4*)g_p1)[i];
        float4 bb = ((const float4*)bias)[tid];
        xn.x = xv.x + a.x + bv.x + bb.x;
        xn.y = xv.y + a.y + bv.y + bb.y;
        xn.z = xv.z + a.z + bv.z + bb.z;
        xn.w = xv.w + a.w + bv.w + bb.w;
        ((float4*)g_x)[i] = xn;
        sdata[tid] = xn;
        local = xn.x + xn.y + xn.z + xn.w;
    }
    if (!doLN) return;   // uniform across block
    float mean = blockSum256(local) * (1.0f/TD);
    float lv = 0.f;
    if (tid < 192){
        float4 t = sdata[tid];
        float a0 = t.x-mean, a1 = t.y-mean, a2 = t.z-mean, a3 = t.w-mean;
        lv = a0*a0 + a1*a1 + a2*a2 + a3*a3;
    }
    float var = blockSum256(lv) * (1.0f/TD);
    float rstd = rsqrtf(var + LN_EPS);
    if (tid < 192){
        float4 gg = ((const float4*)g)[tid];
        float4 bb = ((const float4*)b)[tid];
        float o0 = (xn.x-mean)*rstd*gg.x + bb.x;
        float o1 = (xn.y-mean)*rstd*gg.y + bb.y;
        float o2 = (xn.z-mean)*rstd*gg.z + bb.z;
        float o3 = (xn.w-mean)*rstd*gg.w + bb.w;
        __half2* orow = (__half2*)(g_h + (size_t)row*TD);
        orow[tid*2    ] = __floats2half2_rn(o0, o1);
        orow[tid*2 + 1] = __floats2half2_rn(o2, o3);
    }
}

// ---------------- layernorm (vectorized, fp16 out) ----------------
__global__ void __launch_bounds__(256)
layernorm_kernel(const float* __restrict__ x, __half* __restrict__ out,
                 const float* __restrict__ g, const float* __restrict__ b){
    __shared__ float4 sdata[192];
    int row = blockIdx.x;
    int tid = threadIdx.x;
    const float4* xr = (const float4*)(x + (size_t)row*TD);
    float4 v = make_float4(0.f,0.f,0.f,0.f);
    float local = 0.f;
    if (tid < 192){ v = xr[tid]; sdata[tid] = v; local = v.x + v.y + v.z + v.w; }
    float mean = blockSum256(local) * (1.0f/TD);
    float lv = 0.f;
    if (tid < 192){
        float4 t = sdata[tid];
        float a0 = t.x-mean, a1 = t.y-mean, a2 = t.z-mean, a3 = t.w-mean;
        lv = a0*a0 + a1*a1 + a2*a2 + a3*a3;
    }
    float var = blockSum256(lv) * (1.0f/TD);
    float rstd = rsqrtf(var + LN_EPS);
    if (tid < 192){
        float4 gg = ((const float4*)g)[tid];
        float4 bb = ((const float4*)b)[tid];
        float o0 = (v.x-mean)*rstd*gg.x + bb.x;
        float o1 = (v.y-mean)*rstd*gg.y + bb.y;
        float o2 = (v.z-mean)*rstd*gg.z + bb.z;
        float o3 = (v.w-mean)*rstd*gg.w + bb.w;
        __half2* orow = (__half2*)(out + (size_t)row*TD);
        orow[tid*2    ] = __floats2half2_rn(o0, o1);
        orow[tid*2 + 1] = __floats2half2_rn(o2, o3);
    }
}

// ---------------- QKV projection via fp16 MMA (fp16 out, q pre-scaled) ----------------
__global__ void __launch_bounds__(256)
qkv16_kernel(const float* __restrict__ bq, const float* __restrict__ bk,
             const float* __restrict__ bv, int layer){
    __shared__ __half  Hs[128][72];
    __shared__ __half2 Ws[3][32][72];

    int h = blockIdx.y;
    int m0 = blockIdx.x * 128;
    int tid = threadIdx.x;
    int warp = tid >> 5, lane = tid & 31;

    int hrow = tid >> 1;
    int hcol = (tid & 1) * 32;
    const __half* hSrc = g_h + (size_t)(m0 + hrow)*TD + h*64 + hcol;
    int hSz = (m0 + hrow < M_TOK) ? 16 : 0;
    #pragma unroll
    for (int c = 0; c < 4; c++)
        cp_async16(smem_u32(&Hs[hrow][hcol + c*8]), hSrc + c*8, hSz);

    size_t head_off = ((size_t)layer*NH + h)*QKV_HEAD_H2;
    #pragma unroll
    for (int mt = 0; mt < 3; mt++){
        const __half2* wsrc = g_wQKV[mt] + head_off;
        #pragma unroll
        for (int c = 0; c < 2; c++){
            int ch = tid + c*256;
            int r  = ch >> 4;
            int c4 = (ch & 15) * 4;
            cp_async16(smem_u32(&Ws[mt][r][c4]), wsrc + r*64 + c4, 16);
        }
    }
    cp_commit();
    cp_wait<0>();
    __syncthreads();

    float cf[3][8][4];
    #pragma unroll
    for (int mt=0;mt<3;mt++)
        #pragma unroll
        for (int ni=0;ni<8;ni++)
            #pragma unroll
            for (int j=0;j<4;j++) cf[mt][ni][j] = 0.f;

    int q2 = (lane & 3) * 2;
    #pragma unroll
    for (int ks = 0; ks < 64; ks += 16){
        uint32_t af[4];
        int m = warp*16 + (lane >> 2);
        af[0] = *(const uint32_t*)&Hs[m  ][ks + q2];
        af[1] = *(const uint32_t*)&Hs[m+8][ks + q2];
        af[2] = *(const uint32_t*)&Hs[m  ][ks + 8 + q2];
        af[3] = *(const uint32_t*)&Hs[m+8][ks + 8 + q2];
        int k2r = (ks >> 1) + (lane & 3);
        #pragma unroll
        for (int mt = 0; mt < 3; mt++){
            #pragma unroll
            for (int ni = 0; ni < 8; ni++){
                int n = ni*8 + (lane >> 2);
                uint32_t b0 = *(const uint32_t*)&Ws[mt][k2r    ][n];
                uint32_t b1 = *(const uint32_t*)&Ws[mt][k2r + 4][n];
                mma16816(cf[mt][ni], af, b0, b1);
            }
        }
    }

    const float* bp[3] = {bq + h*64, bk + h*64, bv + h*64};
    __half* op[3] = {g_q, g_k, g_v};
    float scale[3] = {ATT_SCALE, 1.0f, 1.0f};
    #pragma unroll
    for (int mt = 0; mt < 3; mt++){
        #pragma unroll
        for (int ni = 0; ni < 8; ni++){
            int cbase = ni*8 + (lane & 3)*2;
            #pragma unroll
            for (int hh = 0; hh < 2; hh++){
                int r = m0 + warp*16 + (lane >> 2) + hh*8;
                if (r >= M_TOK) continue;
                int e = cbase;
                __half2 hv = __floats2half2_rn(
                    (cf[mt][ni][hh*2+0] + bp[mt][e    ]) * scale[mt],
                    (cf[mt][ni][hh*2+1] + bp[mt][e + 1]) * scale[mt]);
                *(__half2*)&op[mt][(size_t)r*TD + h*64 + e] = hv;
            }
        }
    }
}

// ---------------- flash attention via fp16 MMA ----------------
#define FATT_SMEM ((128*72 + 208*72 + 64*216)*2)

__global__ void __launch_bounds__(256)
fattn_kernel(){
    extern __shared__ __half fsm[];
    __half* Qs = fsm;                    // [128][72]
    __half* Ks = Qs + 128*72;            // [208][72]
    __half* Vt = Ks + 208*72;            // [64][216]

    int h = blockIdx.x, b = blockIdx.y, qz = blockIdx.z;
    int tid = threadIdx.x, warp = tid >> 5, lane = tid & 31;
    size_t base = ((size_t)b*TT)*TD + h*64;
    int q0cta = qz*128;

    for (int i = tid; i < 128*8; i += 256){
        int r = i >> 3, c = i & 7;
        int qrow = q0cta + r;
        const __half* src = g_q + base + (size_t)((qrow < TT) ? qrow : 0)*TD + c*8;
        cp_async16(smem_u32(&Qs[r*72 + c*8]), src, (qrow < TT) ? 16 : 0);
    }
    for (int i = tid; i < 208*8; i += 256){
        int r = i >> 3, c = i & 7;
        const __half* src = g_k + base + (size_t)((r < TT) ? r : 0)*TD + c*8;
        cp_async16(smem_u32(&Ks[r*72 + c*8]), src, (r < TT) ? 16 : 0);
    }
    cp_commit();
    for (int i = tid; i < 208*32; i += 256){
        int r = i >> 5, dp = (i & 31)*2;
        __half2 hv;
        if (r < TT) hv = *(const __half2*)(g_v + base + (size_t)r*TD + dp);
        else        hv = __floats2half2_rn(0.f, 0.f);
        Vt[ dp     *216 + r] = __low2half(hv);
        Vt[(dp + 1)*216 + r] = __high2half(hv);
    }
    cp_wait<0>();
    __syncthreads();

    int q0 = q0cta + warp*16;
    if (q0 >= TT) return;

    int r = lane >> 2, c2 = (lane & 3)*2;

    uint32_t aq[4][4];
    #pragma unroll
    for (int ks = 0; ks < 4; ks++){
        int qr = warp*16 + r;
        aq[ks][0] = *(const uint32_t*)&Qs[ qr     *72 + ks*16 + c2];
        aq[ks][1] = *(const uint32_t*)&Qs[(qr + 8)*72 + ks*16 + c2];
        aq[ks][2] = *(const uint32_t*)&Qs[ qr     *72 + ks*16 + c2 + 8];
        aq[ks][3] = *(const uint32_t*)&Qs[(qr + 8)*72 + ks*16 + c2 + 8];
    }

    float m0 = -1e30f, m1 = -1e30f, l0 = 0.f, l1 = 0.f;
    float o[8][4];
    #pragma unroll
    for (int nt=0;nt<8;nt++)
        #pragma unroll
        for (int j=0;j<4;j++) o[nt][j] = 0.f;

    for (int kt = 0; kt < 13; kt++){
        float s0[4] = {0.f,0.f,0.f,0.f};
        float s1[4] = {0.f,0.f,0.f,0.f};
        #pragma unroll
        for (int ks = 0; ks < 4; ks++){
            int kr = kt*16 + r;
            uint32_t b00 = *(const uint32_t*)&Ks[ kr     *72 + ks*16 + c2];
            uint32_t b01 = *(const uint32_t*)&Ks[ kr     *72 + ks*16 + c2 + 8];
            uint32_t b10 = *(const uint32_t*)&Ks[(kr + 8)*72 + ks*16 + c2];
            uint32_t b11 = *(const uint32_t*)&Ks[(kr + 8)*72 + ks*16 + c2 + 8];
            mma16816(s0, aq[ks], b00, b01);
            mma16816(s1, aq[ks], b10, b11);
        }
        if (kt == 12){
            #pragma unroll
            for (int j = 0; j < 2; j++){
                if (192 + c2 + j >= TT){ s0[j] = -1e30f; s0[j+2] = -1e30f; }
                if (200 + c2 + j >= TT){ s1[j] = -1e30f; s1[j+2] = -1e30f; }
            }
        }
        float tm0 = fmaxf(fmaxf(s0[0], s0[1]), fmaxf(s1[0], s1[1]));
        float tm1 = fmaxf(fmaxf(s0[2], s0[3]), fmaxf(s1[2], s1[3]));
        tm0 = fmaxf(tm0, __shfl_xor_sync(0xffffffffu, tm0, 1));
        tm0 = fmaxf(tm0, __shfl_xor_sync(0xffffffffu, tm0, 2));
        tm1 = fmaxf(tm1, __shfl_xor_sync(0xffffffffu, tm1, 1));
        tm1 = fmaxf(tm1, __shfl_xor_sync(0xffffffffu, tm1, 2));
        float nm0 = fmaxf(m0, tm0), nm1 = fmaxf(m1, tm1);
        float cr0 = __expf(m0 - nm0), cr1 = __expf(m1 - nm1);
        m0 = nm0; m1 = nm1;
        float p00 = __expf(s0[0] - m0), p01 = __expf(s0[1] - m0);
        float p02 = __expf(s0[2] - m1), p03 = __expf(s0[3] - m1);
        float p10 = __expf(s1[0] - m0), p11 = __expf(s1[1] - m0);
        float p12 = __expf(s1[2] - m1), p13 = __expf(s1[3] - m1);
        float sum0 = p00 + p01 + p10 + p11;
        float sum1 = p02 + p03 + p12 + p13;
        sum0 += __shfl_xor_sync(0xffffffffu, sum0, 1);
        sum0 += __shfl_xor_sync(0xffffffffu, sum0, 2);
        sum1 += __shfl_xor_sync(0xffffffffu, sum1, 1);
        sum1 += __shfl_xor_sync(0xffffffffu, sum1, 2);
        l0 = l0*cr0 + sum0;
        l1 = l1*cr1 + sum1;
        #pragma unroll
        for (int nt = 0; nt < 8; nt++){
            o[nt][0] *= cr0; o[nt][1] *= cr0;
            o[nt][2] *= cr1; o[nt][3] *= cr1;
        }
        uint32_t pa[4];
        __half2 h0 = __floats2half2_rn(p00, p01);
        __half2 h1 = __floats2half2_rn(p02, p03);
        __half2 h2 = __floats2half2_rn(p10, p11);
        __half2 h3 = __floats2half2_rn(p12, p13);
        pa[0] = *(uint32_t*)&h0; pa[1] = *(uint32_t*)&h1;
        pa[2] = *(uint32_t*)&h2; pa[3] = *(uint32_t*)&h3;
        #pragma unroll
        for (int nt = 0; nt < 8; nt++){
            int vrow = nt*8 + r;
            uint32_t b0 = *(const uint32_t*)&Vt[vrow*216 + kt*16 + c2];
            uint32_t b1 = *(const uint32_t*)&Vt[vrow*216 + kt*16 + c2 + 8];
            mma16816(o[nt], pa, b0, b1);
        }
    }

    float inv0 = 1.0f / l0, inv1 = 1.0f / l1;
    int qa = q0 + r, qb = q0 + r + 8;
    #pragma unroll
    for (int nt = 0; nt < 8; nt++){
        int d = nt*8 + c2;
        if (qa < TT){
            g_x[base + (size_t)qa*TD + d    ] += o[nt][0]*inv0;
            g_x[base + (size_t)qa*TD + d + 1] += o[nt][1]*inv0;
        }
        if (qb < TT){
            g_x[base + (size_t)qb*TD + d    ] += o[nt][2]*inv1;
            g_x[base + (size_t)qb*TD + d + 1] += o[nt][3]*inv1;
        }
    }
}

// ---------------- fp16 GEMM: k-tile 32, 3-stage ring, 2 CTA/SM, optional split-K ----------------
// (R14 configuration — proven best)
#define H16_STAGE_BYTES (128*40*2 + 16*136*4)
#define H16_SMEM (3*H16_STAGE_BYTES)

__global__ void __launch_bounds__(256, 2)
h16gemm_kernel(const __half* __restrict__ A, int lda,
               const __half2* __restrict__ Bp,
               const float* __restrict__ bias, void* __restrict__ C,
               float* __restrict__ Cp1,
               int M, int N, int K, int epi){
    extern __shared__ char smg[];

    int tid  = threadIdx.x;
    int lane = tid & 31;
    int warp = tid >> 5;
    int warpM = warp >> 1;
    int warpN = warp & 1;
    int row0 = blockIdx.y * 128;
    int col0 = blockIdx.x * 128;
    int kOff = blockIdx.z * K;

    float cf[2][8][4];
    #pragma unroll
    for (int mi=0;mi<2;mi++)
        #pragma unroll
        for (int ni=0;ni<8;ni++)
            #pragma unroll
            for (int j=0;j<4;j++) cf[mi][ni][j] = 0.f;

    int arow = tid >> 1;
    int acol = (tid & 1) * 16;
    const __half* aSrc = A + (size_t)(row0 + arow)*lda + kOff + acol;
    int aSz = (row0 + arow < M) ? 16 : 0;
    int bkr = tid >> 4;
    int bcc = (tid & 15) * 8;
    const __half2* bSrc = Bp + (size_t)(bkr + blockIdx.z*(K >> 1))*N + col0 + bcc;

    int KT = K >> 5;

    #pragma unroll
    for (int s = 0; s < 2; s++){
        __half*  As = (__half*)(smg + s*H16_STAGE_BYTES);
        __half2* Bs = (__half2*)(smg + s*H16_STAGE_BYTES + 128*40*2);
        int kk = s << 5;
        int k2 = s << 4;
        #pragma unroll
        for (int c = 0; c < 2; c++){
            cp_async16(smem_u32(&As[arow*40 + acol + c*8]), aSrc + kk + c*8, aSz);
            cp_async16(smem_u32(&Bs[bkr*136 + bcc + c*4]), bSrc + (size_t)k2*N + c*4, 16);
        }
        cp_commit();
    }

    int stage = 0;
    for (int kt = 0; kt < KT; kt++){
        cp_wait<1>();
        __syncthreads();

        if (kt + 2 < KT){
            int st = stage + 2; if (st >= 3) st -= 3;
            __half*  Asp = (__half*)(smg + st*H16_STAGE_BYTES);
            __half2* Bsp = (__half2*)(smg + st*H16_STAGE_BYTES + 128*40*2);
            int kk = (kt + 2) << 5;
            int k2 = (kt + 2) << 4;
            #pragma unroll
            for (int c = 0; c < 2; c++){
                cp_async16(smem_u32(&Asp[arow*40 + acol + c*8]), aSrc + kk + c*8, aSz);
                cp_async16(smem_u32(&Bsp[bkr*136 + bcc + c*4]), bSrc + (size_t)k2*N + c*4, 16);
            }
        }
        cp_commit();

        const __half*  As = (const __half*)(smg + stage*H16_STAGE_BYTES);
        const __half2* Bs = (const __half2*)(smg + stage*H16_STAGE_BYTES + 128*40*2);

        int q2 = (lane & 3) * 2;
        #pragma unroll
        for (int ks = 0; ks < 32; ks += 16){
            uint32_t af[2][4], bf[8][2];
            #pragma unroll
            for (int mi = 0; mi < 2; mi++){
                int m = warpM*32 + mi*16 + (lane >> 2);
                af[mi][0] = *(const uint32_t*)&As[m*40 + ks + q2];
                af[mi][1] = *(const uint32_t*)&As[(m+8)*40 + ks + q2];
                af[mi][2] = *(const uint32_t*)&As[m*40 + ks + 8 + q2];
                af[mi][3] = *(const uint32_t*)&As[(m+8)*40 + ks + 8 + q2];
            }
            int k2r = (ks >> 1) + (lane & 3);
            #pragma unroll
            for (int ni = 0; ni < 8; ni++){
                int n = warpN*64 + ni*8 + (lane >> 2);
                bf[ni][0] = *(const uint32_t*)&Bs[k2r*136 + n];
                bf[ni][1] = *(const uint32_t*)&Bs[(k2r + 4)*136 + n];
            }
            #pragma unroll
            for (int mi = 0; mi < 2; mi++)
                #pragma unroll
                for (int ni = 0; ni < 8; ni++)
                    mma16816(cf[mi][ni], af[mi], bf[ni][0], bf[ni][1]);
        }
        stage++; if (stage >= 3) stage = 0;
    }

    float* Cf = (float*)C;
    __half* Ch = (__half*)C;
    float* Cpart = (blockIdx.z == 0) ? (float*)C : Cp1;
    #pragma unroll
    for (int mi = 0; mi < 2; mi++){
        int rbase = row0 + warpM*32 + mi*16 + (lane >> 2);
        #pragma unroll
        for (int ni = 0; ni < 8; ni++){
            int cbase = col0 + warpN*64 + ni*8 + (lane & 3)*2;
            #pragma unroll
            for (int hh = 0; hh < 2; hh++){
                int r = rbase + hh*8;
                if (r >= M) continue;
                #pragma unroll
                for (int jj = 0; jj < 2; jj++){
                    int c = cbase + jj;
                    size_t idx = (size_t)r*N + c;
                    if (epi == 3){
                        Cpart[idx] = cf[mi][ni][hh*2+jj];
                    } else {
                        float v = cf[mi][ni][hh*2+jj] + bias[c];
                        if (epi == 1){
                            Ch[idx] = __float2half_rn(0.5f*v*(1.0f + erff(v*0.70710678118654752f)));
                        } else if (epi == 2){
                            Cf[idx] += v;
                        } else {
                            Cf[idx] = v;
                        }
                    }
                }
            }
        }
    }
}

// ---------------- classifier head + softmax ----------------
__global__ void classifier_kernel(const float* __restrict__ Wout, const float* __restrict__ bout,
                                  float* __restrict__ out){
    __shared__ float xs[TD];
    __shared__ float lg[OD];
    int b = blockIdx.x;
    int tid = threadIdx.x;
    for (int i = tid; i < TD; i += 256) xs[i] = g_x[((size_t)b*TT)*TD + i];
    __syncthreads();
    for (int n = tid; n < OD; n += 256){
        float s = bout[n];
        for (int d = 0; d < TD; d++) s = fmaf(xs[d], Wout[(size_t)d*OD + n], s);
        lg[n] = s;
    }
    __syncthreads();
    float lm = -1e30f;
    for (int n = tid; n < OD; n += 256) lm = fmaxf(lm, lg[n]);
    lm = blockMax256(lm);
    float ls = 0.f;
    for (int n = tid; n < OD; n += 256){
        float e = expf(lg[n] - lm);
        lg[n] = e;
        ls += e;
    }
    ls = blockSum256(ls);
    float inv = 1.0f / ls;
    for (int n = tid; n < OD; n += 256) out[(size_t)b*OD + n] = lg[n] * inv;
}

// ---------------- host orchestration ----------------
extern "C" void kernel_launch(void* const* d_in, const int* in_sizes, int n_in,
                              void* d_out, int out_size){
    const float* images  = (const float*)d_in[0];
    const float* W_embed = (const float*)d_in[1];
    const float* b_embed = (const float*)d_in[2];
    const float* v_class = (const float*)d_in[3];
    const float* ln1_g   = (const float*)d_in[4];
    const float* ln1_b   = (const float*)d_in[5];
    const float* ln2_g   = (const float*)d_in[6];
    const float* ln2_b   = (const float*)d_in[7];
    const float* Wq      = (const float*)d_in[8];
    const float* bq      = (const float*)d_in[9];
    const float* Wk      = (const float*)d_in[10];
    const float* bk      = (const float*)d_in[11];
    const float* Wv      = (const float*)d_in[12];
    const float* bv      = (const float*)d_in[13];
    const float* Wm1     = (const float*)d_in[14];
    const float* bm1     = (const float*)d_in[15];
    const float* Wm2     = (const float*)d_in[16];
    const float* bm2     = (const float*)d_in[17];
    const float* Wout    = (const float*)d_in[18];
    const float* bout    = (const float*)d_in[19];
    float* out = (float*)d_out;

    float *px, *ptok, *pp0, *pp1;
    __half *ph, *pmlp, *ppatch;
    __half2 *pwH, *pwQKV0, *pwQKV1, *pwQKV2;
    cudaGetSymbolAddress((void**)&px, g_x);
    cudaGetSymbolAddress((void**)&ph, g_h);
    cudaGetSymbolAddress((void**)&pmlp, g_mlp);
    cudaGetSymbolAddress((void**)&ppatch, g_patches);
    cudaGetSymbolAddress((void**)&ptok, g_tok);
    cudaGetSymbolAddress((void**)&pp0, g_p0);
    cudaGetSymbolAddress((void**)&pp1, g_p1);
    cudaGetSymbolAddress((void**)&pwH, g_wH);
    {
        __half2* base;
        cudaGetSymbolAddress((void**)&base, g_wQKV);
        pwQKV0 = base;
        pwQKV1 = base + (size_t)NB*NH*QKV_HEAD_H2;
        pwQKV2 = base + 2*(size_t)NB*NH*QKV_HEAD_H2;
    }

    cudaFuncSetAttribute(h16gemm_kernel, cudaFuncAttributeMaxDynamicSharedMemorySize, H16_SMEM);
    cudaFuncSetAttribute(fattn_kernel, cudaFuncAttributeMaxDynamicSharedMemorySize, FATT_SMEM);

    // pack weights once per launch
    packB_kernel<<<2048, 256>>>(W_embed, pwH + WH_EMBED_OFF, (size_t)TD/2, TD);
    packB_kernel<<<16384, 256>>>(Wm1, pwH + WH_M1_OFF, (size_t)NB*TD/2, MD);
    packB_kernel<<<16384, 256>>>(Wm2, pwH + WH_M2_OFF, (size_t)NB*MD/2, TD);
    pack_qkv_kernel<<<1152, 256>>>(Wq, pwQKV0);
    pack_qkv_kernel<<<1152, 256>>>(Wk, pwQKV1);
    pack_qkv_kernel<<<1152, 256>>>(Wv, pwQKV2);

    // patchify + embed
    patchify_kernel<<<(M_PATCH*TD + 255)/256, 256>>>(images);
    {
        dim3 g(TD/128, (M_PATCH + 127)/128, 1);
        h16gemm_kernel<<<g, 256, H16_SMEM>>>(ppatch, TD, pwH + WH_EMBED_OFF, b_embed,
                                             ptok, nullptr, M_PATCH, TD, TD, 0);
    }
    assemble_kernel<<<(M_TOK*TD + 255)/256, 256>>>(v_class, ptok);

    // LN1 for layer 0
    layernorm_kernel<<<M_TOK, 256>>>(px, ph, ln1_g, ln1_b);

    for (int l = 0; l < NB; l++){
        {
            dim3 g((M_TOK + 127)/128, NH);
            qkv16_kernel<<<g, 256>>>(bq + (size_t)l*NH*64, bk + (size_t)l*NH*64,
                                     bv + (size_t)l*NH*64, l);
        }
        fattn_kernel<<<dim3(NH, BSZ, 2), 256, FATT_SMEM>>>();
        layernorm_kernel<<<M_TOK, 256>>>(px, ph, ln2_g + l*TD, ln2_b + l*TD);
        {
            dim3 g(MD/128, (M_TOK + 127)/128, 1);
            h16gemm_kernel<<<g, 256, H16_SMEM>>>(ph, TD, pwH + WH_M1_OFF + (size_t)l*(TD/2)*MD,
                                                 bm1 + (size_t)l*MD, pmlp, nullptr,
                                                 M_TOK, MD, TD, 1);
        }
        {
            dim3 g(TD/128, (M_TOK + 127)/128, 2);
            h16gemm_kernel<<<g, 256, H16_SMEM>>>(pmlp, MD, pwH + WH_M2_OFF + (size_t)l*(MD/2)*TD,
                                                 nullptr, pp0, pp1,
                                                 M_TOK, TD, MD/2, 3);
        }
        if (l + 1 < NB){
            mlpres_ln_kernel<<<M_TOK, 256>>>(bm2 + (size_t)l*TD,
                                             ln1_g + (size_t)(l+1)*TD,
                                             ln1_b + (size_t)(l+1)*TD, 1);
        } else {
            mlpres_ln_kernel<<<M_TOK, 256>>>(bm2 + (size_t)l*TD, nullptr, nullptr, 0);
        }
    }

    classifier_kernel<<<BSZ, 256>>>(Wout, bout, out);
}